// round 12
// baseline (speedup 1.0000x reference)
#include <cuda_runtime.h>

// Problem constants (fixed shapes from reference setup_inputs)
#define BB 64
#define CC 256
#define TT 2048
#define NROWS (BB * CC)             // 16384 rows of 2048 floats
#define N_PER_CH (BB * TT)          // 131072 samples per channel
#define CT (CC * TT)                // 524288
#define EPS 1e-4f
#define NBLK 592                    // 148 SMs x 4 co-resident blocks (GB300 has 152 SMs)
#define NTHR 256
#define NTILES ((CC / 32) * (TT / 32))   // 512 transpose tiles
#define MAXROWS 32                  // max rows per block = ceil(16384/592) = 28

// Device scratch (allocation-free rule: __device__ globals; zero-initialized)
__device__ float g_rowsum[NROWS];   // per-(b,c)-row sum      (no atomics, no reset)
__device__ float g_rowsq[NROWS];    // per-(b,c)-row sum of squares
__device__ float g_gT[CT];          // gamma transposed to [C, T]
__device__ float g_bT[CT];          // beta  transposed to [C, T]
__device__ unsigned g_arrive;       // barrier arrival counter (self-resetting)
__device__ unsigned g_release;      // barrier generation (monotonic across replays)

// 256-bit store with L2 evict_first: the 134 MB output stream victimizes its
// own lines instead of flushing the L2-resident x (proven win in R8/R9).
__device__ __forceinline__ void st8_evict_first(float* p, float4 a, float4 b) {
    asm volatile("st.global.L2::evict_first.v8.b32 [%0], {%1,%2,%3,%4,%5,%6,%7,%8};"
                 :: "l"(p),
                    "r"(__float_as_uint(a.x)), "r"(__float_as_uint(a.y)),
                    "r"(__float_as_uint(a.z)), "r"(__float_as_uint(a.w)),
                    "r"(__float_as_uint(b.x)), "r"(__float_as_uint(b.y)),
                    "r"(__float_as_uint(b.z)), "r"(__float_as_uint(b.w))
                 : "memory");
}

// ---------------------------------------------------------------------------
// Single persistent kernel (sawtooth L2 scheme).
//   Phase 1a: transpose gamma/beta -> g_gT/g_bT  (blocks 0..511, one tile each)
//   Phase 1b: per-row (b,c) sum/sumsq, rows strided by NBLK (forward order)
//   Device-wide barrier (generation counter: graph-replay safe, no host reset)
//   Phase 2a: channel stats for ALL owned rows (k = warp, warp+8, ...)
//   Phase 2b: normalize owned rows in REVERSE order -> freshest L2 lines first
// ---------------------------------------------------------------------------
__global__ __launch_bounds__(NTHR, 4) void fused_kernel(
    const float* __restrict__ x,
    const float* __restrict__ gamma,
    const float* __restrict__ beta,
    float* __restrict__ out)
{
    const int bid = blockIdx.x;
    const int tid = threadIdx.x;
    const int warp = tid >> 5;
    const int lane = tid & 31;

    __shared__ float sg[32][33];
    __shared__ float sb[32][33];
    __shared__ float ws[8], wq[8];
    __shared__ float s_mean[MAXROWS], s_rs[MAXROWS];
    __shared__ unsigned s_gen;

    // Read barrier generation BEFORE doing any work / arriving.
    if (tid == 0) s_gen = *(volatile unsigned*)&g_release;
    __syncthreads();
    const unsigned gen = s_gen;

    // ---- Phase 1a: one 32x32 gamma/beta transpose tile per block ------------
    if (bid < NTILES) {
        const int cBase = (bid & 7) * 32;        // CC/32 = 8
        const int tBase = (bid >> 3) * 32;
        const int tx = tid & 31;
        const int ty = tid >> 5;
#pragma unroll
        for (int r = 0; r < 4; r++) {
            const int tl = ty + r * 8;
            sg[tl][tx] = __ldg(&gamma[(tBase + tl) * CC + cBase + tx]);
            sb[tl][tx] = __ldg(&beta [(tBase + tl) * CC + cBase + tx]);
        }
        __syncthreads();
#pragma unroll
        for (int r = 0; r < 4; r++) {
            const int cl = ty + r * 8;
            g_gT[(cBase + cl) * TT + tBase + tx] = sg[tx][cl];
            g_bT[(cBase + cl) * TT + tBase + tx] = sb[tx][cl];
        }
    }

    // ---- Phase 1b: row sums (rows bid, bid+NBLK, ...; forward order) --------
    int nrows = 0;
    for (int row = bid; row < NROWS; row += NBLK) nrows++;

    for (int k = 0; k < nrows; k++) {
        const int row = bid + k * NBLK;
        const float4* p = (const float4*)(x + (size_t)row * TT);

        float4 v0 = __ldg(&p[tid]);
        float4 v1 = __ldg(&p[tid + 256]);
        float s  = ((v0.x + v0.y) + (v0.z + v0.w)) + ((v1.x + v1.y) + (v1.z + v1.w));
        float sq = (v0.x * v0.x + v0.y * v0.y) + (v0.z * v0.z + v0.w * v0.w)
                 + (v1.x * v1.x + v1.y * v1.y) + (v1.z * v1.z + v1.w * v1.w);

#pragma unroll
        for (int off = 16; off > 0; off >>= 1) {
            s  += __shfl_down_sync(0xFFFFFFFFu, s,  off);
            sq += __shfl_down_sync(0xFFFFFFFFu, sq, off);
        }
        __syncthreads();                    // ws/wq reuse across iterations
        if (lane == 0) { ws[warp] = s; wq[warp] = sq; }
        __syncthreads();
        if (tid == 0) {
            float ts = 0.0f, tq = 0.0f;
#pragma unroll
            for (int w = 0; w < 8; w++) { ts += ws[w]; tq += wq[w]; }
            g_rowsum[row] = ts;
            g_rowsq[row]  = tq;
        }
    }

    // ---- Device-wide barrier (self-resetting, replay-safe) -------------------
    __threadfence();
    __syncthreads();
    if (tid == 0) {
        const unsigned t = atomicAdd(&g_arrive, 1u);
        if (t == NBLK - 1u) {
            g_arrive = 0u;                  // reset for next replay
            __threadfence();
            atomicAdd(&g_release, 1u);      // open the gate
        }
        while (*(volatile unsigned*)&g_release == gen) { __nanosleep(128); }
    }
    __syncthreads();
    __threadfence();

    // ---- Phase 2a: stats for ALL owned rows (warp w: k = w, w+8, w+16, ...) --
    for (int k = warp; k < nrows; k += 8) {
        const int row = bid + k * NBLK;
        const int c = row & (CC - 1);
        float s = __ldcg(&g_rowsum[lane * CC + c]) + __ldcg(&g_rowsum[(lane + 32) * CC + c]);
        float q = __ldcg(&g_rowsq [lane * CC + c]) + __ldcg(&g_rowsq [(lane + 32) * CC + c]);
#pragma unroll
        for (int off = 16; off > 0; off >>= 1) {
            s += __shfl_down_sync(0xFFFFFFFFu, s, off);
            q += __shfl_down_sync(0xFFFFFFFFu, q, off);
        }
        if (lane == 0) {
            const float inv_n = 1.0f / (float)N_PER_CH;
            const float mean = s * inv_n;
            const float var = fmaxf(q * inv_n - mean * mean, 0.0f);
            s_mean[k] = mean;
            s_rs[k]   = rsqrtf(var + EPS);
        }
    }
    __syncthreads();

    // ---- Phase 2b: normalize owned rows in REVERSE (freshest L2 lines first) -
    for (int k = nrows - 1; k >= 0; k--) {
        const int row = bid + k * NBLK;
        const int c = row & (CC - 1);
        const float mean = s_mean[k];
        const float rs   = s_rs[k];

        const size_t off = (size_t)row * TT + (size_t)tid * 8;
        const float4* xp = (const float4*)(x + off);
        const float4* gp = (const float4*)(g_gT + (size_t)c * TT) + tid * 2;
        const float4* bp = (const float4*)(g_bT + (size_t)c * TT) + tid * 2;

        const float4 xv0 = xp[0];
        const float4 xv1 = xp[1];
        const float4 gv0 = __ldcg(&gp[0]);
        const float4 gv1 = __ldcg(&gp[1]);
        const float4 bv0 = __ldcg(&bp[0]);
        const float4 bv1 = __ldcg(&bp[1]);

        float4 o0, o1;
        o0.x = fmaf((xv0.x - mean) * rs, gv0.x, bv0.x);
        o0.y = fmaf((xv0.y - mean) * rs, gv0.y, bv0.y);
        o0.z = fmaf((xv0.z - mean) * rs, gv0.z, bv0.z);
        o0.w = fmaf((xv0.w - mean) * rs, gv0.w, bv0.w);
        o1.x = fmaf((xv1.x - mean) * rs, gv1.x, bv1.x);
        o1.y = fmaf((xv1.y - mean) * rs, gv1.y, bv1.y);
        o1.z = fmaf((xv1.z - mean) * rs, gv1.z, bv1.z);
        o1.w = fmaf((xv1.w - mean) * rs, gv1.w, bv1.w);
        st8_evict_first(out + off, o0, o1);
    }
}

// ---------------------------------------------------------------------------
extern "C" void kernel_launch(void* const* d_in, const int* in_sizes, int n_in,
                              void* d_out, int out_size) {
    const float* x = (const float*)d_in[0];
    const float* gamma = (const float*)d_in[1];
    const float* beta = (const float*)d_in[2];
    float* out = (float*)d_out;

    fused_kernel<<<NBLK, NTHR>>>(x, gamma, beta, out);
}

// round 13
// speedup vs baseline: 1.1487x; 1.1487x over previous
#include <cuda_runtime.h>

// Problem constants (fixed shapes from reference setup_inputs)
#define BB 64
#define CC 256
#define TT 2048
#define NROWS (BB * CC)             // 16384 rows of 2048 floats
#define N_PER_CH (BB * TT)          // 131072 samples per channel
#define CT (CC * TT)                // 524288
#define EPS 1e-4f
#define NBLK 592                    // 148 SMs x 4 co-resident blocks
#define NTHR 256
#define NTILES ((CC / 32) * (TT / 32))   // 512 transpose tiles
#define MAXROWS 32                  // max rows per block = ceil(16384/592) = 28

// Device scratch (allocation-free rule: __device__ globals)
__device__ float g_rowsum[NROWS];   // per-(b,c)-row sum (no atomics, no reset)
__device__ float g_rowsq[NROWS];    // per-(b,c)-row sum of squares
__device__ float g_gT[CT];          // gamma transposed to [C, T]
__device__ float g_bT[CT];          // beta  transposed to [C, T]
__device__ unsigned g_arrive;       // barrier arrival counter (self-resetting)
__device__ unsigned g_release;      // barrier generation (monotonic across replays)

// 256-bit store with L2 evict_first: the 134 MB output stream victimizes its
// own lines instead of flushing the L2-resident x.
__device__ __forceinline__ void st8_evict_first(float* p, float4 a, float4 b) {
    asm volatile("st.global.L2::evict_first.v8.b32 [%0], {%1,%2,%3,%4,%5,%6,%7,%8};"
                 :: "l"(p),
                    "r"(__float_as_uint(a.x)), "r"(__float_as_uint(a.y)),
                    "r"(__float_as_uint(a.z)), "r"(__float_as_uint(a.w)),
                    "r"(__float_as_uint(b.x)), "r"(__float_as_uint(b.y)),
                    "r"(__float_as_uint(b.z)), "r"(__float_as_uint(b.w))
                 : "memory");
}

// ---------------------------------------------------------------------------
// Single persistent kernel (sawtooth L2 scheme), latency-optimized phase 1.
//   Phase 1a: transpose gamma/beta -> g_gT/g_bT  (blocks 0..511, one tile each)
//   Phase 1b: WARP-PER-ROW sum/sumsq: no __syncthreads, MLP~16 streaming loads
//   Device-wide barrier (generation counter: graph-replay safe)
//   Phase 2a: channel stats for all owned rows (warp-strided)
//   Phase 2b: normalize owned rows in REVERSE order (freshest L2 lines first)
// ---------------------------------------------------------------------------
__global__ __launch_bounds__(NTHR, 4) void fused_kernel(
    const float* __restrict__ x,
    const float* __restrict__ gamma,
    const float* __restrict__ beta,
    float* __restrict__ out)
{
    const int bid = blockIdx.x;
    const int tid = threadIdx.x;
    const int warp = tid >> 5;
    const int lane = tid & 31;

    __shared__ float sg[32][33];
    __shared__ float sb[32][33];
    __shared__ float s_mean[MAXROWS], s_rs[MAXROWS];
    __shared__ unsigned s_gen;

    // Read barrier generation BEFORE doing any work / arriving.
    if (tid == 0) s_gen = *(volatile unsigned*)&g_release;
    __syncthreads();
    const unsigned gen = s_gen;

    int nrows = 0;
    for (int row = bid; row < NROWS; row += NBLK) nrows++;

    // ---- Phase 1a: one 32x32 gamma/beta transpose tile per block ------------
    if (bid < NTILES) {
        const int cBase = (bid & 7) * 32;        // CC/32 = 8
        const int tBase = (bid >> 3) * 32;
        const int tx = tid & 31;
        const int ty = tid >> 5;
#pragma unroll
        for (int r = 0; r < 4; r++) {
            const int tl = ty + r * 8;
            sg[tl][tx] = __ldg(&gamma[(tBase + tl) * CC + cBase + tx]);
            sb[tl][tx] = __ldg(&beta [(tBase + tl) * CC + cBase + tx]);
        }
        __syncthreads();
#pragma unroll
        for (int r = 0; r < 4; r++) {
            const int cl = ty + r * 8;
            g_gT[(cBase + cl) * TT + tBase + tx] = sg[tx][cl];
            g_bT[(cBase + cl) * TT + tBase + tx] = sb[tx][cl];
        }
    }

    // ---- Phase 1b: warp-per-row sums (forward order, no block syncs) --------
    for (int k = warp; k < nrows; k += 8) {
        const int row = bid + k * NBLK;
        const float4* p = (const float4*)(x + (size_t)row * TT);

        float s = 0.0f, sq = 0.0f;
#pragma unroll
        for (int i = 0; i < 16; i++) {
            const float4 v = __ldg(&p[lane + 32 * i]);
            s  += (v.x + v.y) + (v.z + v.w);
            sq += (v.x * v.x + v.y * v.y) + (v.z * v.z + v.w * v.w);
        }
#pragma unroll
        for (int off = 16; off > 0; off >>= 1) {
            s  += __shfl_down_sync(0xFFFFFFFFu, s,  off);
            sq += __shfl_down_sync(0xFFFFFFFFu, sq, off);
        }
        if (lane == 0) {
            g_rowsum[row] = s;
            g_rowsq[row]  = sq;
        }
    }

    // ---- Device-wide barrier (self-resetting, replay-safe) -------------------
    __threadfence();
    __syncthreads();
    if (tid == 0) {
        const unsigned t = atomicAdd(&g_arrive, 1u);
        if (t == NBLK - 1u) {
            g_arrive = 0u;                  // reset for next replay
            __threadfence();
            atomicAdd(&g_release, 1u);      // open the gate
        }
        while (*(volatile unsigned*)&g_release == gen) { __nanosleep(128); }
    }
    __syncthreads();
    __threadfence();

    // ---- Phase 2a: stats for ALL owned rows (warp w: k = w, w+8, ...) -------
    for (int k = warp; k < nrows; k += 8) {
        const int row = bid + k * NBLK;
        const int c = row & (CC - 1);
        float s = __ldcg(&g_rowsum[lane * CC + c]) + __ldcg(&g_rowsum[(lane + 32) * CC + c]);
        float q = __ldcg(&g_rowsq [lane * CC + c]) + __ldcg(&g_rowsq [(lane + 32) * CC + c]);
#pragma unroll
        for (int off = 16; off > 0; off >>= 1) {
            s += __shfl_down_sync(0xFFFFFFFFu, s, off);
            q += __shfl_down_sync(0xFFFFFFFFu, q, off);
        }
        if (lane == 0) {
            const float inv_n = 1.0f / (float)N_PER_CH;
            const float mean = s * inv_n;
            const float var = fmaxf(q * inv_n - mean * mean, 0.0f);
            s_mean[k] = mean;
            s_rs[k]   = rsqrtf(var + EPS);
        }
    }
    __syncthreads();

    // ---- Phase 2b: normalize owned rows in REVERSE (freshest L2 lines first) -
    for (int k = nrows - 1; k >= 0; k--) {
        const int row = bid + k * NBLK;
        const int c = row & (CC - 1);
        const float mean = s_mean[k];
        const float rs   = s_rs[k];

        const size_t off = (size_t)row * TT + (size_t)tid * 8;
        const float4* xp = (const float4*)(x + off);
        const float4* gp = (const float4*)(g_gT + (size_t)c * TT) + tid * 2;
        const float4* bp = (const float4*)(g_bT + (size_t)c * TT) + tid * 2;

        const float4 xv0 = xp[0];
        const float4 xv1 = xp[1];
        const float4 gv0 = __ldcg(&gp[0]);
        const float4 gv1 = __ldcg(&gp[1]);
        const float4 bv0 = __ldcg(&bp[0]);
        const float4 bv1 = __ldcg(&bp[1]);

        float4 o0, o1;
        o0.x = fmaf((xv0.x - mean) * rs, gv0.x, bv0.x);
        o0.y = fmaf((xv0.y - mean) * rs, gv0.y, bv0.y);
        o0.z = fmaf((xv0.z - mean) * rs, gv0.z, bv0.z);
        o0.w = fmaf((xv0.w - mean) * rs, gv0.w, bv0.w);
        o1.x = fmaf((xv1.x - mean) * rs, gv1.x, bv1.x);
        o1.y = fmaf((xv1.y - mean) * rs, gv1.y, bv1.y);
        o1.z = fmaf((xv1.z - mean) * rs, gv1.z, bv1.z);
        o1.w = fmaf((xv1.w - mean) * rs, gv1.w, bv1.w);
        st8_evict_first(out + off, o0, o1);
    }
}

// ---------------------------------------------------------------------------
extern "C" void kernel_launch(void* const* d_in, const int* in_sizes, int n_in,
                              void* d_out, int out_size) {
    const float* x = (const float*)d_in[0];
    const float* gamma = (const float*)d_in[1];
    const float* beta = (const float*)d_in[2];
    float* out = (float*)d_out;

    fused_kernel<<<NBLK, NTHR>>>(x, gamma, beta, out);
}

// round 14
// speedup vs baseline: 1.4967x; 1.3030x over previous
#include <cuda_runtime.h>

// Problem constants (fixed shapes from reference setup_inputs)
#define BB 64
#define CC 256
#define TT 2048
#define NROWS (BB * CC)             // 16384 rows of 2048 floats
#define N_PER_CH (BB * TT)          // 131072 samples per channel
#define CT (CC * TT)                // 524288
#define EPS 1e-4f
#define NTILES ((CC / 32) * (TT / 32))   // 512 transpose tiles
#define RBLK 2048                   // rowsum blocks (8 warps x 1 row each)
#define BSPLIT 16
#define B_PER_NORM (BB / BSPLIT)    // 4 images per norm block

// Device scratch (allocation-free rule: __device__ globals)
__device__ float g_rowsum[NROWS];   // per-(b,c)-row sum (no atomics, no reset)
__device__ float g_rowsq[NROWS];    // per-(b,c)-row sum of squares
__device__ float g_gT[CT];          // gamma transposed to [C, T]
__device__ float g_bT[CT];          // beta  transposed to [C, T]

// 256-bit store with L2 evict_first: the 134 MB output stream victimizes its
// own lines instead of flushing the L2-resident x (proven in R8/R9).
__device__ __forceinline__ void st8_evict_first(float* p, float4 a, float4 b) {
    asm volatile("st.global.L2::evict_first.v8.b32 [%0], {%1,%2,%3,%4,%5,%6,%7,%8};"
                 :: "l"(p),
                    "r"(__float_as_uint(a.x)), "r"(__float_as_uint(a.y)),
                    "r"(__float_as_uint(a.z)), "r"(__float_as_uint(a.w)),
                    "r"(__float_as_uint(b.x)), "r"(__float_as_uint(b.y)),
                    "r"(__float_as_uint(b.z)), "r"(__float_as_uint(b.w))
                 : "memory");
}

// ---------------------------------------------------------------------------
// Kernel 1: transpose (blocks 0..511) + warp-per-row sums (blocks 512..2559).
// Each rowsum warp owns ONE row: 16 independent float4 loads per lane, pure
// warp-shuffle reduce, zero block syncs, no atomics. Rows ascend with bid
// (forward sweep -> the tail of x is freshest in L2 when kernel 2 starts).
// ---------------------------------------------------------------------------
__global__ __launch_bounds__(256) void stats_kernel(
    const float* __restrict__ x,
    const float* __restrict__ gamma,
    const float* __restrict__ beta)
{
    const int bid = blockIdx.x;
    const int tid = threadIdx.x;
    const int warp = tid >> 5;
    const int lane = tid & 31;

    if (bid < NTILES) {
        // ---- gamma/beta transpose: one 32x32 tile ----
        __shared__ float sg[32][33];
        __shared__ float sb[32][33];
        const int cBase = (bid & 7) * 32;        // CC/32 = 8
        const int tBase = (bid >> 3) * 32;
        const int tx = tid & 31;
        const int ty = tid >> 5;
#pragma unroll
        for (int r = 0; r < 4; r++) {
            const int tl = ty + r * 8;
            sg[tl][tx] = __ldg(&gamma[(tBase + tl) * CC + cBase + tx]);
            sb[tl][tx] = __ldg(&beta [(tBase + tl) * CC + cBase + tx]);
        }
        __syncthreads();
#pragma unroll
        for (int r = 0; r < 4; r++) {
            const int cl = ty + r * 8;
            g_gT[(cBase + cl) * TT + tBase + tx] = sg[tx][cl];
            g_bT[(cBase + cl) * TT + tBase + tx] = sb[tx][cl];
        }
        return;
    }

    // ---- warp-per-row sum/sumsq ----
    const int row = (bid - NTILES) * 8 + warp;   // 2048 blocks x 8 warps = 16384
    const float4* p = (const float4*)(x + (size_t)row * TT);

    float s = 0.0f, sq = 0.0f;
#pragma unroll
    for (int i = 0; i < 16; i++) {
        const float4 v = __ldg(&p[lane + 32 * i]);
        s  += (v.x + v.y) + (v.z + v.w);
        sq += (v.x * v.x + v.y * v.y) + (v.z * v.z + v.w * v.w);
    }
#pragma unroll
    for (int off = 16; off > 0; off >>= 1) {
        s  += __shfl_down_sync(0xFFFFFFFFu, s,  off);
        sq += __shfl_down_sync(0xFFFFFFFFu, sq, off);
    }
    if (lane == 0) {
        g_rowsum[row] = s;
        g_rowsq[row]  = sq;
    }
}

// ---------------------------------------------------------------------------
// Kernel 2: per-(channel, batch-group) normalize with inline stats.
// Grid (CC, BSPLIT), y REVERSED -> walks x backward vs kernel 1's forward
// sweep (sawtooth: first wave lands on the freshest L2 lines).
// Warp 0 computes channel stats from g_rowsum (64 KB, L2-hot). Each thread
// holds its 8 gT/bT values in registers across the 4 images.
// out: v8 evict_first stores (output victimizes itself, not resident x).
// ---------------------------------------------------------------------------
__global__ __launch_bounds__(256) void norm_kernel(
    const float* __restrict__ x,
    float* __restrict__ out)
{
    const int c  = blockIdx.x;                       // channel
    const int b0 = (BSPLIT - 1 - blockIdx.y) * B_PER_NORM;  // reversed groups
    const int tid = threadIdx.x;
    const int lane = tid & 31;

    __shared__ float s_mean, s_rs;

    if (tid < 32) {
        float s = __ldg(&g_rowsum[lane * CC + c]) + __ldg(&g_rowsum[(lane + 32) * CC + c]);
        float q = __ldg(&g_rowsq [lane * CC + c]) + __ldg(&g_rowsq [(lane + 32) * CC + c]);
#pragma unroll
        for (int off = 16; off > 0; off >>= 1) {
            s += __shfl_down_sync(0xFFFFFFFFu, s, off);
            q += __shfl_down_sync(0xFFFFFFFFu, q, off);
        }
        if (lane == 0) {
            const float inv_n = 1.0f / (float)N_PER_CH;
            const float mean = s * inv_n;
            const float var = fmaxf(q * inv_n - mean * mean, 0.0f);
            s_mean = mean;
            s_rs   = rsqrtf(var + EPS);
        }
    }

    // gT/bT segment for this channel (read 16x across y-groups -> L2 hits)
    const float4* gp = (const float4*)(g_gT + (size_t)c * TT) + tid * 2;
    const float4* bp = (const float4*)(g_bT + (size_t)c * TT) + tid * 2;
    const float4 gv0 = __ldg(&gp[0]);
    const float4 gv1 = __ldg(&gp[1]);
    const float4 bv0 = __ldg(&bp[0]);
    const float4 bv1 = __ldg(&bp[1]);

    __syncthreads();
    const float rs = s_rs;
    const float mrs = s_mean * rs;                   // o = (x*rs - mrs)*g + b

    // Normalize 4 images in DESCENDING b (continue the backward sweep)
#pragma unroll
    for (int bb = B_PER_NORM - 1; bb >= 0; bb--) {
        const size_t off = (size_t)(b0 + bb) * CT + (size_t)c * TT + (size_t)tid * 8;
        const float4* xp = (const float4*)(x + off);
        const float4 xv0 = xp[0];                    // default: hit/refresh or allocate
        const float4 xv1 = xp[1];

        float4 o0, o1;
        o0.x = fmaf(fmaf(xv0.x, rs, -mrs), gv0.x, bv0.x);
        o0.y = fmaf(fmaf(xv0.y, rs, -mrs), gv0.y, bv0.y);
        o0.z = fmaf(fmaf(xv0.z, rs, -mrs), gv0.z, bv0.z);
        o0.w = fmaf(fmaf(xv0.w, rs, -mrs), gv0.w, bv0.w);
        o1.x = fmaf(fmaf(xv1.x, rs, -mrs), gv1.x, bv1.x);
        o1.y = fmaf(fmaf(xv1.y, rs, -mrs), gv1.y, bv1.y);
        o1.z = fmaf(fmaf(xv1.z, rs, -mrs), gv1.z, bv1.z);
        o1.w = fmaf(fmaf(xv1.w, rs, -mrs), gv1.w, bv1.w);
        st8_evict_first(out + off, o0, o1);
    }
}

// ---------------------------------------------------------------------------
extern "C" void kernel_launch(void* const* d_in, const int* in_sizes, int n_in,
                              void* d_out, int out_size) {
    const float* x = (const float*)d_in[0];
    const float* gamma = (const float*)d_in[1];
    const float* beta = (const float*)d_in[2];
    float* out = (float*)d_out;

    stats_kernel<<<NTILES + RBLK, 256>>>(x, gamma, beta);
    norm_kernel<<<dim3(CC, BSPLIT), 256>>>(x, out);
}

// round 15
// speedup vs baseline: 1.5284x; 1.0212x over previous
#include <cuda_runtime.h>

// Problem constants (fixed shapes from reference setup_inputs)
#define BB 64
#define CC 256
#define TT 2048
#define NROWS (BB * CC)             // 16384 rows of 2048 floats
#define N_PER_CH (BB * TT)          // 131072 samples per channel
#define CT (CC * TT)                // 524288
#define EPS 1e-4f
#define NTILES ((CC / 32) * (TT / 32))   // 512 transpose tiles
#define RBLK 2048                   // rowsum blocks (8 warps x 1 row each)
#define BSPLIT 16
#define B_PER_NORM (BB / BSPLIT)    // 4 images per norm block

// Device scratch (allocation-free rule: __device__ globals)
__device__ float g_rowsum[NROWS];   // per-(b,c)-row sum (no atomics, no reset)
__device__ float g_rowsq[NROWS];    // per-(b,c)-row sum of squares
__device__ float g_gT[CT];          // gamma transposed to [C, T]
__device__ float g_bT[CT];          // beta  transposed to [C, T]

// 256-bit accesses with explicit L2 eviction priority. The sawtooth traversal
// (stats forward, norm backward) makes high hit rates ACHIEVABLE; these hints
// decide the victim contest: x lines (evict_last) survive, out write
// allocations (evict_first) victimize each other.
__device__ __forceinline__ void ld8_evict_last(const float* p, float4& a, float4& b) {
    unsigned r0, r1, r2, r3, r4, r5, r6, r7;
    asm volatile("ld.global.nc.L2::evict_last.v8.b32 {%0,%1,%2,%3,%4,%5,%6,%7}, [%8];"
                 : "=r"(r0), "=r"(r1), "=r"(r2), "=r"(r3),
                   "=r"(r4), "=r"(r5), "=r"(r6), "=r"(r7)
                 : "l"(p));
    a.x = __uint_as_float(r0); a.y = __uint_as_float(r1);
    a.z = __uint_as_float(r2); a.w = __uint_as_float(r3);
    b.x = __uint_as_float(r4); b.y = __uint_as_float(r5);
    b.z = __uint_as_float(r6); b.w = __uint_as_float(r7);
}
__device__ __forceinline__ void st8_evict_first(float* p, float4 a, float4 b) {
    asm volatile("st.global.L2::evict_first.v8.b32 [%0], {%1,%2,%3,%4,%5,%6,%7,%8};"
                 :: "l"(p),
                    "r"(__float_as_uint(a.x)), "r"(__float_as_uint(a.y)),
                    "r"(__float_as_uint(a.z)), "r"(__float_as_uint(a.w)),
                    "r"(__float_as_uint(b.x)), "r"(__float_as_uint(b.y)),
                    "r"(__float_as_uint(b.z)), "r"(__float_as_uint(b.w))
                 : "memory");
}

// ---------------------------------------------------------------------------
// Kernel 1: transpose (blocks 0..511) + warp-per-row sums (blocks 512..2559).
// Each rowsum warp owns ONE row: 8 v8 loads per lane, pure warp-shuffle
// reduce, zero block syncs, no atomics. Rows ascend with bid (forward sweep).
// x reads: evict_last (build/refresh the protected resident copy).
// ---------------------------------------------------------------------------
__global__ __launch_bounds__(256) void stats_kernel(
    const float* __restrict__ x,
    const float* __restrict__ gamma,
    const float* __restrict__ beta)
{
    const int bid = blockIdx.x;
    const int tid = threadIdx.x;
    const int warp = tid >> 5;
    const int lane = tid & 31;

    if (bid < NTILES) {
        // ---- gamma/beta transpose: one 32x32 tile ----
        __shared__ float sg[32][33];
        __shared__ float sb[32][33];
        const int cBase = (bid & 7) * 32;        // CC/32 = 8
        const int tBase = (bid >> 3) * 32;
        const int tx = tid & 31;
        const int ty = tid >> 5;
#pragma unroll
        for (int r = 0; r < 4; r++) {
            const int tl = ty + r * 8;
            sg[tl][tx] = __ldg(&gamma[(tBase + tl) * CC + cBase + tx]);
            sb[tl][tx] = __ldg(&beta [(tBase + tl) * CC + cBase + tx]);
        }
        __syncthreads();
#pragma unroll
        for (int r = 0; r < 4; r++) {
            const int cl = ty + r * 8;
            g_gT[(cBase + cl) * TT + tBase + tx] = sg[tx][cl];
            g_bT[(cBase + cl) * TT + tBase + tx] = sb[tx][cl];
        }
        return;
    }

    // ---- warp-per-row sum/sumsq (8 x v8 loads per lane) ----
    const int row = (bid - NTILES) * 8 + warp;   // 2048 blocks x 8 warps = 16384
    const float* p = x + (size_t)row * TT;

    float s = 0.0f, sq = 0.0f;
#pragma unroll
    for (int i = 0; i < 8; i++) {
        float4 v0, v1;
        ld8_evict_last(p + lane * 8 + i * 256, v0, v1);
        s  += ((v0.x + v0.y) + (v0.z + v0.w)) + ((v1.x + v1.y) + (v1.z + v1.w));
        sq += (v0.x * v0.x + v0.y * v0.y) + (v0.z * v0.z + v0.w * v0.w)
            + (v1.x * v1.x + v1.y * v1.y) + (v1.z * v1.z + v1.w * v1.w);
    }
#pragma unroll
    for (int off = 16; off > 0; off >>= 1) {
        s  += __shfl_down_sync(0xFFFFFFFFu, s,  off);
        sq += __shfl_down_sync(0xFFFFFFFFu, sq, off);
    }
    if (lane == 0) {
        g_rowsum[row] = s;
        g_rowsq[row]  = sq;
    }
}

// ---------------------------------------------------------------------------
// Kernel 2: per-(channel, batch-group) normalize with inline stats.
// Grid (CC, BSPLIT), y REVERSED -> walks x backward vs kernel 1's forward
// sweep (sawtooth). Warp 0 computes channel stats from g_rowsum (64 KB,
// L2-hot). Each thread holds its 8 gT/bT values in registers across 4 images.
// x: v8 evict_last (protected). out: v8 evict_first (self-victimizing).
// ---------------------------------------------------------------------------
__global__ __launch_bounds__(256) void norm_kernel(
    const float* __restrict__ x,
    float* __restrict__ out)
{
    const int c  = blockIdx.x;                       // channel
    const int b0 = (BSPLIT - 1 - blockIdx.y) * B_PER_NORM;  // reversed groups
    const int tid = threadIdx.x;
    const int lane = tid & 31;

    __shared__ float s_mean, s_rs;

    if (tid < 32) {
        float s = __ldg(&g_rowsum[lane * CC + c]) + __ldg(&g_rowsum[(lane + 32) * CC + c]);
        float q = __ldg(&g_rowsq [lane * CC + c]) + __ldg(&g_rowsq [(lane + 32) * CC + c]);
#pragma unroll
        for (int off = 16; off > 0; off >>= 1) {
            s += __shfl_down_sync(0xFFFFFFFFu, s, off);
            q += __shfl_down_sync(0xFFFFFFFFu, q, off);
        }
        if (lane == 0) {
            const float inv_n = 1.0f / (float)N_PER_CH;
            const float mean = s * inv_n;
            const float var = fmaxf(q * inv_n - mean * mean, 0.0f);
            s_mean = mean;
            s_rs   = rsqrtf(var + EPS);
        }
    }

    // gT/bT segment for this channel (read 16x across y-groups -> L2 hits)
    const float4* gp = (const float4*)(g_gT + (size_t)c * TT) + tid * 2;
    const float4* bp = (const float4*)(g_bT + (size_t)c * TT) + tid * 2;
    const float4 gv0 = __ldg(&gp[0]);
    const float4 gv1 = __ldg(&gp[1]);
    const float4 bv0 = __ldg(&bp[0]);
    const float4 bv1 = __ldg(&bp[1]);

    __syncthreads();
    const float rs = s_rs;
    const float mrs = s_mean * rs;                   // o = (x*rs - mrs)*g + b

    // Normalize 4 images in DESCENDING b (continue the backward sweep)
#pragma unroll
    for (int bb = B_PER_NORM - 1; bb >= 0; bb--) {
        const size_t off = (size_t)(b0 + bb) * CT + (size_t)c * TT + (size_t)tid * 8;
        float4 xv0, xv1;
        ld8_evict_last(x + off, xv0, xv1);

        float4 o0, o1;
        o0.x = fmaf(fmaf(xv0.x, rs, -mrs), gv0.x, bv0.x);
        o0.y = fmaf(fmaf(xv0.y, rs, -mrs), gv0.y, bv0.y);
        o0.z = fmaf(fmaf(xv0.z, rs, -mrs), gv0.z, bv0.z);
        o0.w = fmaf(fmaf(xv0.w, rs, -mrs), gv0.w, bv0.w);
        o1.x = fmaf(fmaf(xv1.x, rs, -mrs), gv1.x, bv1.x);
        o1.y = fmaf(fmaf(xv1.y, rs, -mrs), gv1.y, bv1.y);
        o1.z = fmaf(fmaf(xv1.z, rs, -mrs), gv1.z, bv1.z);
        o1.w = fmaf(fmaf(xv1.w, rs, -mrs), gv1.w, bv1.w);
        st8_evict_first(out + off, o0, o1);
    }
}

// ---------------------------------------------------------------------------
extern "C" void kernel_launch(void* const* d_in, const int* in_sizes, int n_in,
                              void* d_out, int out_size) {
    const float* x = (const float*)d_in[0];
    const float* gamma = (const float*)d_in[1];
    const float* beta = (const float*)d_in[2];
    float* out = (float*)d_out;

    stats_kernel<<<NTILES + RBLK, 256>>>(x, gamma, beta);
    norm_kernel<<<dim3(CC, BSPLIT), 256>>>(x, out);
}